// round 4
// baseline (speedup 1.0000x reference)
#include <cuda_runtime.h>
#include <cuda_fp16.h>
#include <cstdint>
#include <cstddef>

// ============================================================================
// TurboQuantLinear: out[t,n] = sum_k x[t,k] * W_eff[n,k]
//   W_eff[n, g*128+k] = (norms[n,g]/sqrt(128)) * sum_j codes[n,g,j]*R[g,j,k]
// Target is sm_100 (no 'a' suffix -> no tcgen05/TMA). Use ldmatrix + mma.sync
// fp16 with fp32 accum, 2-term split: x_f16 * (W_hi + W_lo).
// ============================================================================

constexpr int TOKENS = 8192;
constexpr int KDIM   = 4096;
constexpr int NDIM   = 4096;
constexpr float INV_SCALE = 0.08838834764831845f; // 1/sqrt(128)

// ---- scratch (device globals; allocation is forbidden) ---------------------
__device__ __align__(16) __half g_xh[(size_t)TOKENS * KDIM];   // 64 MB
__device__ __align__(16) __half g_wh[(size_t)NDIM * KDIM];     // 32 MB
__device__ __align__(16) __half g_wl[(size_t)NDIM * KDIM];     // 32 MB

// ---- PTX helpers (sm_80-level only; target is sm_100 non-'a') --------------
__device__ __forceinline__ uint32_t smem_u32(const void* p) {
    uint32_t a;
    asm("{ .reg .u64 t; cvta.to.shared.u64 t, %1; cvt.u32.u64 %0, t; }"
        : "=r"(a) : "l"(p));
    return a;
}

__device__ __forceinline__ void cp16(uint32_t s, const void* g) {
    asm volatile("cp.async.cg.shared.global [%0], [%1], 16;" :: "r"(s), "l"(g));
}
#define CP_COMMIT() asm volatile("cp.async.commit_group;" ::: "memory")
#define CP_WAIT(n)  asm volatile("cp.async.wait_group %0;" :: "n"(n) : "memory")

__device__ __forceinline__ void ldsm_x4(uint32_t (&r)[4], uint32_t addr) {
    asm volatile("ldmatrix.sync.aligned.m8n8.x4.shared.b16 {%0,%1,%2,%3}, [%4];"
        : "=r"(r[0]), "=r"(r[1]), "=r"(r[2]), "=r"(r[3]) : "r"(addr));
}

__device__ __forceinline__ void mma16816(float (&d)[4], const uint32_t (&a)[4],
                                         uint32_t b0, uint32_t b1) {
    asm volatile("mma.sync.aligned.m16n8k16.row.col.f32.f16.f16.f32 "
        "{%0,%1,%2,%3}, {%4,%5,%6,%7}, {%8,%9}, {%0,%1,%2,%3};"
        : "+f"(d[0]), "+f"(d[1]), "+f"(d[2]), "+f"(d[3])
        : "r"(a[0]), "r"(a[1]), "r"(a[2]), "r"(a[3]), "r"(b0), "r"(b1));
}

__device__ __forceinline__ uint32_t pack_h2(__half a, __half b) {
    return (uint32_t)__half_as_ushort(a) | ((uint32_t)__half_as_ushort(b) << 16);
}
__device__ __forceinline__ void split_h(float v, __half& h, __half& l) {
    h = __float2half_rn(v);
    l = __float2half_rn(v - __half2float(h));
}

// ---------------------------------------------------------------------------
// Kernel 1: x fp32 -> fp16
// ---------------------------------------------------------------------------
__global__ void __launch_bounds__(256) convert_x_kernel(const float4* __restrict__ x) {
    size_t i = (size_t)blockIdx.x * blockDim.x + threadIdx.x;  // 0 .. 8388607
    float4 v = x[i];
    uint2 p;
    p.x = pack_h2(__float2half_rn(v.x), __float2half_rn(v.y));
    p.y = pack_h2(__float2half_rn(v.z), __float2half_rn(v.w));
    *(uint2*)(g_xh + 4 * i) = p;
}

// ---------------------------------------------------------------------------
// Kernel 2: W_eff fp32 build, split to fp16 hi/lo
//   grid (128 row-chunks of 32 rows, 32 groups), block 128, 80KB smem
// ---------------------------------------------------------------------------
__global__ void __launch_bounds__(128, 1) prep_kernel(
        const int* __restrict__ packed, const float* __restrict__ cb,
        const float* __restrict__ norms, const float* __restrict__ rot) {
    extern __shared__ float sm[];
    float* Rs = sm;            // [128 j][128 k] fp32, 64KB
    float* Cs = sm + 16384;    // [32 r][128 j] fp32, 16KB
    __shared__ float cbs[16];

    const int t = threadIdx.x;
    const int g = blockIdx.y;
    const int row0 = blockIdx.x * 32;

    if (t < 16) cbs[t] = cb[t];
    const float4* rg = (const float4*)(rot + (size_t)g * 16384);
    float4* Rs4 = (float4*)Rs;
#pragma unroll 8
    for (int i = t; i < 4096; i += 128) Rs4[i] = rg[i];
    __syncthreads();   // cbs visible

#pragma unroll 4
    for (int i = t; i < 2048; i += 128) {
        int r = i >> 6, ii = i & 63;
        int v = packed[(size_t)(row0 + r) * 2048 + g * 64 + ii] & 0xFF;
        Cs[r * 128 + 2 * ii]     = cbs[v & 0xF];
        Cs[r * 128 + 2 * ii + 1] = cbs[(v >> 4) & 0xF];
    }
    __syncthreads();

    const int tx = t & 31;        // k-quad
    const int ty = t >> 5;        // rows ty*8 .. ty*8+7
    const int kq = tx * 4;

    float acc[8][4];
#pragma unroll
    for (int r = 0; r < 8; r++)
#pragma unroll
        for (int q = 0; q < 4; q++) acc[r][q] = 0.f;

    for (int j = 0; j < 128; j += 4) {
        float4 R0 = *(const float4*)&Rs[(j + 0) * 128 + kq];
        float4 R1 = *(const float4*)&Rs[(j + 1) * 128 + kq];
        float4 R2 = *(const float4*)&Rs[(j + 2) * 128 + kq];
        float4 R3 = *(const float4*)&Rs[(j + 3) * 128 + kq];
#pragma unroll
        for (int r = 0; r < 8; r++) {
            float4 c = *(const float4*)&Cs[(ty * 8 + r) * 128 + j];
            acc[r][0] += c.x * R0.x + c.y * R1.x + c.z * R2.x + c.w * R3.x;
            acc[r][1] += c.x * R0.y + c.y * R1.y + c.z * R2.y + c.w * R3.y;
            acc[r][2] += c.x * R0.z + c.y * R1.z + c.z * R2.z + c.w * R3.z;
            acc[r][3] += c.x * R0.w + c.y * R1.w + c.z * R2.w + c.w * R3.w;
        }
    }

#pragma unroll
    for (int r = 0; r < 8; r++) {
        int n = row0 + ty * 8 + r;
        float s = norms[(size_t)n * 32 + g] * INV_SCALE;
        __half h[4], l[4];
#pragma unroll
        for (int q = 0; q < 4; q++) split_h(acc[r][q] * s, h[q], l[q]);
        size_t o = (size_t)n * 4096 + g * 128 + kq;
        *(uint2*)(g_wh + o) = make_uint2(pack_h2(h[0], h[1]), pack_h2(h[2], h[3]));
        *(uint2*)(g_wl + o) = make_uint2(pack_h2(l[0], l[1]), pack_h2(l[2], l[3]));
    }
}

// ---------------------------------------------------------------------------
// Kernel 3: main GEMM. BM=128 BN=128 BK=32, 4-stage cp.async, mma.sync fp16.
//   Padded smem rows: 32 halves data in 40-half (80B) rows -> conflict-free
//   ldmatrix (row stride 20 words; 8 consecutive rows cover all 32 banks).
// ---------------------------------------------------------------------------
constexpr int STAGES = 4;
constexpr int ROWB   = 80;                 // bytes per smem row (64B data + pad)
constexpr int TILEB  = 128 * ROWB;         // 10240 B per 128x32 tile
constexpr int STG    = 3 * TILEB;          // A | Whi | Wlo
constexpr int GEMM_SMEM = STAGES * STG;    // 122880 B

__global__ void __launch_bounds__(256, 1) gemm_kernel(float* __restrict__ out) {
    extern __shared__ __align__(128) char smem[];
    const uint32_t sb = smem_u32(smem);
    const int tid = threadIdx.x, lid = tid & 31, wid = tid >> 5;
    const int wm = wid & 1, wn = wid >> 1;          // warp grid 2 x 4
    const size_t m0 = (size_t)blockIdx.x * 128;     // mblk fast -> wave shares B band
    const size_t n0 = (size_t)blockIdx.y * 128;

    float acc[4][4][4];
#pragma unroll
    for (int mi = 0; mi < 4; mi++)
#pragma unroll
        for (int ni = 0; ni < 4; ni++)
#pragma unroll
            for (int q = 0; q < 4; q++) acc[mi][ni][q] = 0.f;

    const int r_ld = tid >> 2, c_ld = tid & 3;      // cp.async: 2 rows-chunks/thread/tile

    auto issue = [&](int nk) {
        if (nk < 128) {
            const uint32_t st = sb + (nk % STAGES) * STG;
            const size_t kcol = (size_t)nk * 32;
#pragma unroll
            for (int p = 0; p < 2; p++) {
                int r = r_ld + 64 * p;
                uint32_t so = (uint32_t)(r * ROWB + c_ld * 16);
                size_t go = kcol + (size_t)c_ld * 8;
                cp16(st + so,             g_xh + (m0 + r) * 4096 + go);
                cp16(st + TILEB + so,     g_wh + (n0 + r) * 4096 + go);
                cp16(st + 2 * TILEB + so, g_wl + (n0 + r) * 4096 + go);
            }
        }
        CP_COMMIT();   // always commit (keeps wait_group accounting uniform in tail)
    };

#pragma unroll
    for (int s = 0; s < STAGES - 1; s++) issue(s);

    const int rsel = lid & 15, csel = lid >> 4;

    for (int kt = 0; kt < 128; kt++) {
        CP_WAIT(STAGES - 2);
        __syncthreads();
        issue(kt + STAGES - 1);   // writes slot (kt-1)%4: safe, all warps past sync

        const uint32_t st = sb + (kt % STAGES) * STG;
#pragma unroll
        for (int k16 = 0; k16 < 2; k16++) {
            uint32_t a[4][4], bh[2][4], bl[2][4];
            const uint32_t kadd = (uint32_t)(k16 * 32 + csel * 16);
#pragma unroll
            for (int mi = 0; mi < 4; mi++)
                ldsm_x4(a[mi], st + (wm * 64 + mi * 16 + rsel) * ROWB + kadd);
#pragma unroll
            for (int nh = 0; nh < 2; nh++) {
                uint32_t ba = st + TILEB + (wn * 32 + nh * 16 + rsel) * ROWB + kadd;
                ldsm_x4(bh[nh], ba);
                ldsm_x4(bl[nh], ba + TILEB);
            }
#pragma unroll
            for (int mi = 0; mi < 4; mi++)
#pragma unroll
                for (int ni = 0; ni < 4; ni++) {
                    const int nh = ni >> 1, s2 = ni & 1;
                    mma16816(acc[mi][ni], a[mi], bh[nh][s2], bh[nh][s2 + 2]);
                    mma16816(acc[mi][ni], a[mi], bl[nh][s2], bl[nh][s2 + 2]);
                }
        }
    }

    // epilogue: d frag mapping -> out[t][n]
    const int r0 = lid >> 2, c0 = (lid & 3) * 2;
#pragma unroll
    for (int mi = 0; mi < 4; mi++)
#pragma unroll
        for (int ni = 0; ni < 4; ni++) {
            size_t m = m0 + wm * 64 + mi * 16 + r0;
            size_t n = n0 + wn * 32 + ni * 8 + c0;
            *(float2*)(out + m * 4096 + n) =
                make_float2(acc[mi][ni][0], acc[mi][ni][1]);
            *(float2*)(out + (m + 8) * 4096 + n) =
                make_float2(acc[mi][ni][2], acc[mi][ni][3]);
        }
}

// ---------------------------------------------------------------------------
extern "C" void kernel_launch(void* const* d_in, const int* in_sizes, int n_in,
                              void* d_out, int out_size) {
    const float* x      = (const float*)d_in[0];
    const int*   packed = (const int*)  d_in[1];
    const float* cb     = (const float*)d_in[2];
    const float* norms  = (const float*)d_in[3];
    const float* rot    = (const float*)d_in[4];
    float* out = (float*)d_out;

    cudaFuncSetAttribute(prep_kernel, cudaFuncAttributeMaxDynamicSharedMemorySize, 81920);
    cudaFuncSetAttribute(gemm_kernel, cudaFuncAttributeMaxDynamicSharedMemorySize, GEMM_SMEM);

    convert_x_kernel<<<32768, 256>>>((const float4*)x);
    prep_kernel<<<dim3(128, 32), 128, 81920>>>(packed, cb, norms, rot);
    gemm_kernel<<<dim3(64, 32), 256, GEMM_SMEM>>>(out);
}

// round 5
// speedup vs baseline: 1.8091x; 1.8091x over previous
#include <cuda_runtime.h>
#include <cuda_fp16.h>
#include <cstdint>
#include <cstddef>

// ============================================================================
// TurboQuantLinear: out[t,n] = sum_k x[t,k] * W_eff[n,k]
//   W_eff[n, g*128+k] = (norms[n,g]/sqrt(128)) * sum_j codes[n,g,j]*R[g,j,k]
// sm_100 (no 'a': no tcgen05/TMA). ldmatrix + mma.sync m16n8k16 fp16->fp32.
// R4: single-term fp16 (measured 2-term rel_err 2.08e-4 => 1-term ~2.9e-4,
// safely under 1e-3), CTA tile 128x256, warp tile 64x64.
// ============================================================================

constexpr int TOKENS = 8192;
constexpr int KDIM   = 4096;
constexpr int NDIM   = 4096;
constexpr float INV_SCALE = 0.08838834764831845f; // 1/sqrt(128)

__device__ __align__(16) __half g_xh[(size_t)TOKENS * KDIM];   // 64 MB
__device__ __align__(16) __half g_wh[(size_t)NDIM * KDIM];     // 32 MB

// ---- PTX helpers -----------------------------------------------------------
__device__ __forceinline__ uint32_t smem_u32(const void* p) {
    uint32_t a;
    asm("{ .reg .u64 t; cvta.to.shared.u64 t, %1; cvt.u32.u64 %0, t; }"
        : "=r"(a) : "l"(p));
    return a;
}
__device__ __forceinline__ void cp16(uint32_t s, const void* g) {
    asm volatile("cp.async.cg.shared.global [%0], [%1], 16;" :: "r"(s), "l"(g));
}
#define CP_COMMIT() asm volatile("cp.async.commit_group;" ::: "memory")
#define CP_WAIT(n)  asm volatile("cp.async.wait_group %0;" :: "n"(n) : "memory")

__device__ __forceinline__ void ldsm_x4(uint32_t (&r)[4], uint32_t addr) {
    asm volatile("ldmatrix.sync.aligned.m8n8.x4.shared.b16 {%0,%1,%2,%3}, [%4];"
        : "=r"(r[0]), "=r"(r[1]), "=r"(r[2]), "=r"(r[3]) : "r"(addr));
}
__device__ __forceinline__ void mma16816(float (&d)[4], const uint32_t (&a)[4],
                                         uint32_t b0, uint32_t b1) {
    asm volatile("mma.sync.aligned.m16n8k16.row.col.f32.f16.f16.f32 "
        "{%0,%1,%2,%3}, {%4,%5,%6,%7}, {%8,%9}, {%0,%1,%2,%3};"
        : "+f"(d[0]), "+f"(d[1]), "+f"(d[2]), "+f"(d[3])
        : "r"(a[0]), "r"(a[1]), "r"(a[2]), "r"(a[3]), "r"(b0), "r"(b1));
}
__device__ __forceinline__ uint32_t pack_h2(__half a, __half b) {
    return (uint32_t)__half_as_ushort(a) | ((uint32_t)__half_as_ushort(b) << 16);
}

// ---------------------------------------------------------------------------
// Kernel 1: x fp32 -> fp16
// ---------------------------------------------------------------------------
__global__ void __launch_bounds__(256) convert_x_kernel(const float4* __restrict__ x) {
    size_t i = (size_t)blockIdx.x * blockDim.x + threadIdx.x;
    float4 v = x[i];
    uint2 p;
    p.x = pack_h2(__float2half_rn(v.x), __float2half_rn(v.y));
    p.y = pack_h2(__float2half_rn(v.z), __float2half_rn(v.w));
    *(uint2*)(g_xh + 4 * i) = p;
}

// ---------------------------------------------------------------------------
// Kernel 2: W_eff fp32 build -> fp16
// ---------------------------------------------------------------------------
__global__ void __launch_bounds__(128, 1) prep_kernel(
        const int* __restrict__ packed, const float* __restrict__ cb,
        const float* __restrict__ norms, const float* __restrict__ rot) {
    extern __shared__ float sm[];
    float* Rs = sm;            // [128 j][128 k] fp32, 64KB
    float* Cs = sm + 16384;    // [32 r][128 j] fp32, 16KB
    __shared__ float cbs[16];

    const int t = threadIdx.x;
    const int g = blockIdx.y;
    const int row0 = blockIdx.x * 32;

    if (t < 16) cbs[t] = cb[t];
    const float4* rg = (const float4*)(rot + (size_t)g * 16384);
    float4* Rs4 = (float4*)Rs;
#pragma unroll 8
    for (int i = t; i < 4096; i += 128) Rs4[i] = rg[i];
    __syncthreads();

#pragma unroll 4
    for (int i = t; i < 2048; i += 128) {
        int r = i >> 6, ii = i & 63;
        int v = packed[(size_t)(row0 + r) * 2048 + g * 64 + ii] & 0xFF;
        Cs[r * 128 + 2 * ii]     = cbs[v & 0xF];
        Cs[r * 128 + 2 * ii + 1] = cbs[(v >> 4) & 0xF];
    }
    __syncthreads();

    const int tx = t & 31;
    const int ty = t >> 5;
    const int kq = tx * 4;

    float acc[8][4];
#pragma unroll
    for (int r = 0; r < 8; r++)
#pragma unroll
        for (int q = 0; q < 4; q++) acc[r][q] = 0.f;

    for (int j = 0; j < 128; j += 4) {
        float4 R0 = *(const float4*)&Rs[(j + 0) * 128 + kq];
        float4 R1 = *(const float4*)&Rs[(j + 1) * 128 + kq];
        float4 R2 = *(const float4*)&Rs[(j + 2) * 128 + kq];
        float4 R3 = *(const float4*)&Rs[(j + 3) * 128 + kq];
#pragma unroll
        for (int r = 0; r < 8; r++) {
            float4 c = *(const float4*)&Cs[(ty * 8 + r) * 128 + j];
            acc[r][0] += c.x * R0.x + c.y * R1.x + c.z * R2.x + c.w * R3.x;
            acc[r][1] += c.x * R0.y + c.y * R1.y + c.z * R2.y + c.w * R3.y;
            acc[r][2] += c.x * R0.z + c.y * R1.z + c.z * R2.z + c.w * R3.z;
            acc[r][3] += c.x * R0.w + c.y * R1.w + c.z * R2.w + c.w * R3.w;
        }
    }

#pragma unroll
    for (int r = 0; r < 8; r++) {
        int n = row0 + ty * 8 + r;
        float s = norms[(size_t)n * 32 + g] * INV_SCALE;
        __half h[4];
#pragma unroll
        for (int q = 0; q < 4; q++) h[q] = __float2half_rn(acc[r][q] * s);
        size_t o = (size_t)n * 4096 + g * 128 + kq;
        *(uint2*)(g_wh + o) = make_uint2(pack_h2(h[0], h[1]), pack_h2(h[2], h[3]));
    }
}

// ---------------------------------------------------------------------------
// Kernel 3: GEMM. BM=128 BN=256 BK=32, 4-stage cp.async, warp tile 64x64.
//   80B padded smem rows -> conflict-free ldmatrix + cp.async.
// ---------------------------------------------------------------------------
constexpr int STAGES = 4;
constexpr int ROWB   = 80;
constexpr int ATILEB = 128 * ROWB;          // 10240
constexpr int BTILEB = 256 * ROWB;          // 20480
constexpr int STG    = ATILEB + BTILEB;     // 30720
constexpr int GEMM_SMEM = STAGES * STG;     // 122880

__global__ void __launch_bounds__(256, 1) gemm_kernel(float* __restrict__ out) {
    extern __shared__ __align__(128) char smem[];
    const uint32_t sb = smem_u32(smem);
    const int tid = threadIdx.x, lid = tid & 31, wid = tid >> 5;
    const int wm = wid & 1, wn = wid >> 1;          // warp grid 2 (M) x 4 (N)
    const size_t m0 = (size_t)blockIdx.x * 128;     // mblk fast: wave shares B in L2
    const size_t n0 = (size_t)blockIdx.y * 256;

    float acc[4][8][4];
#pragma unroll
    for (int mi = 0; mi < 4; mi++)
#pragma unroll
        for (int ni = 0; ni < 8; ni++)
#pragma unroll
            for (int q = 0; q < 4; q++) acc[mi][ni][q] = 0.f;

    const int r_ld = tid >> 2, c_ld = tid & 3;

    auto issue = [&](int nk) {
        if (nk < 128) {
            const uint32_t st = sb + (nk % STAGES) * STG;
            const size_t kcol = (size_t)nk * 32 + (size_t)c_ld * 8;
#pragma unroll
            for (int p = 0; p < 2; p++) {           // A: 128 rows
                int r = r_ld + 64 * p;
                cp16(st + (uint32_t)(r * ROWB + c_ld * 16),
                     g_xh + (m0 + r) * 4096 + kcol);
            }
#pragma unroll
            for (int p = 0; p < 4; p++) {           // B: 256 rows
                int r = r_ld + 64 * p;
                cp16(st + ATILEB + (uint32_t)(r * ROWB + c_ld * 16),
                     g_wh + (n0 + r) * 4096 + kcol);
            }
        }
        CP_COMMIT();
    };

#pragma unroll
    for (int s = 0; s < STAGES - 1; s++) issue(s);

    const int rsel = lid & 15, csel = lid >> 4;

    for (int kt = 0; kt < 128; kt++) {
        CP_WAIT(STAGES - 2);
        __syncthreads();
        issue(kt + STAGES - 1);

        const uint32_t st = sb + (kt % STAGES) * STG;
#pragma unroll
        for (int k16 = 0; k16 < 2; k16++) {
            uint32_t a[4][4], b[4][4];
            const uint32_t kadd = (uint32_t)(k16 * 32 + csel * 16);
#pragma unroll
            for (int mi = 0; mi < 4; mi++)
                ldsm_x4(a[mi], st + (wm * 64 + mi * 16 + rsel) * ROWB + kadd);
#pragma unroll
            for (int nh = 0; nh < 4; nh++)
                ldsm_x4(b[nh], st + ATILEB + (wn * 64 + nh * 16 + rsel) * ROWB + kadd);
#pragma unroll
            for (int mi = 0; mi < 4; mi++)
#pragma unroll
                for (int ni = 0; ni < 8; ni++) {
                    const int nh = ni >> 1, s2 = ni & 1;
                    mma16816(acc[mi][ni], a[mi], b[nh][s2], b[nh][s2 + 2]);
                }
        }
    }

    const int r0 = lid >> 2, c0 = (lid & 3) * 2;
#pragma unroll
    for (int mi = 0; mi < 4; mi++)
#pragma unroll
        for (int ni = 0; ni < 8; ni++) {
            size_t m = m0 + wm * 64 + mi * 16 + r0;
            size_t n = n0 + wn * 64 + ni * 8 + c0;
            *(float2*)(out + m * 4096 + n) =
                make_float2(acc[mi][ni][0], acc[mi][ni][1]);
            *(float2*)(out + (m + 8) * 4096 + n) =
                make_float2(acc[mi][ni][2], acc[mi][ni][3]);
        }
}

// ---------------------------------------------------------------------------
extern "C" void kernel_launch(void* const* d_in, const int* in_sizes, int n_in,
                              void* d_out, int out_size) {
    const float* x      = (const float*)d_in[0];
    const int*   packed = (const int*)  d_in[1];
    const float* cb     = (const float*)d_in[2];
    const float* norms  = (const float*)d_in[3];
    const float* rot    = (const float*)d_in[4];
    float* out = (float*)d_out;

    cudaFuncSetAttribute(prep_kernel, cudaFuncAttributeMaxDynamicSharedMemorySize, 81920);
    cudaFuncSetAttribute(gemm_kernel, cudaFuncAttributeMaxDynamicSharedMemorySize, GEMM_SMEM);

    convert_x_kernel<<<32768, 256>>>((const float4*)x);
    prep_kernel<<<dim3(128, 32), 128, 81920>>>(packed, cb, norms, rot);
    gemm_kernel<<<dim3(64, 16), 256, GEMM_SMEM>>>(out);
}

// round 6
// speedup vs baseline: 2.0195x; 1.1163x over previous
#include <cuda_runtime.h>
#include <cuda_fp16.h>
#include <cstdint>
#include <cstddef>

// ============================================================================
// TurboQuantLinear: out[t,n] = sum_k x[t,k] * W_eff[n,k]
//   W_eff[n, g*128+k] = (norms[n,g]/sqrt(128)) * sum_j codes[n,g,j]*R[g,j,k]
// sm_100 (no 'a': no tcgen05/TMA). ldmatrix + mma.sync m16n8k16 fp16->fp32.
// R6: GEMM restructured: 512 threads / 16 warps (4/SMSP), warp tile 32x64,
// BK=64, 3 stages, 144B padded rows. Discriminates HMMA-rate-bound vs
// LSU/latency-bound; wins if the latter.
// ============================================================================

constexpr int TOKENS = 8192;
constexpr int KDIM   = 4096;
constexpr int NDIM   = 4096;
constexpr float INV_SCALE = 0.08838834764831845f; // 1/sqrt(128)

__device__ __align__(16) __half g_xh[(size_t)TOKENS * KDIM];   // 64 MB
__device__ __align__(16) __half g_wh[(size_t)NDIM * KDIM];     // 32 MB

// ---- PTX helpers -----------------------------------------------------------
__device__ __forceinline__ uint32_t smem_u32(const void* p) {
    uint32_t a;
    asm("{ .reg .u64 t; cvta.to.shared.u64 t, %1; cvt.u32.u64 %0, t; }"
        : "=r"(a) : "l"(p));
    return a;
}
__device__ __forceinline__ void cp16(uint32_t s, const void* g) {
    asm volatile("cp.async.cg.shared.global [%0], [%1], 16;" :: "r"(s), "l"(g));
}
#define CP_COMMIT() asm volatile("cp.async.commit_group;" ::: "memory")
#define CP_WAIT(n)  asm volatile("cp.async.wait_group %0;" :: "n"(n) : "memory")

__device__ __forceinline__ void ldsm_x4(uint32_t (&r)[4], uint32_t addr) {
    asm volatile("ldmatrix.sync.aligned.m8n8.x4.shared.b16 {%0,%1,%2,%3}, [%4];"
        : "=r"(r[0]), "=r"(r[1]), "=r"(r[2]), "=r"(r[3]) : "r"(addr));
}
__device__ __forceinline__ void mma16816(float (&d)[4], const uint32_t (&a)[4],
                                         uint32_t b0, uint32_t b1) {
    asm volatile("mma.sync.aligned.m16n8k16.row.col.f32.f16.f16.f32 "
        "{%0,%1,%2,%3}, {%4,%5,%6,%7}, {%8,%9}, {%0,%1,%2,%3};"
        : "+f"(d[0]), "+f"(d[1]), "+f"(d[2]), "+f"(d[3])
        : "r"(a[0]), "r"(a[1]), "r"(a[2]), "r"(a[3]), "r"(b0), "r"(b1));
}
__device__ __forceinline__ uint32_t pack_h2(__half a, __half b) {
    return (uint32_t)__half_as_ushort(a) | ((uint32_t)__half_as_ushort(b) << 16);
}

// ---------------------------------------------------------------------------
// Kernel 1: x fp32 -> fp16
// ---------------------------------------------------------------------------
__global__ void __launch_bounds__(256) convert_x_kernel(const float4* __restrict__ x) {
    size_t i = (size_t)blockIdx.x * blockDim.x + threadIdx.x;
    float4 v = x[i];
    uint2 p;
    p.x = pack_h2(__float2half_rn(v.x), __float2half_rn(v.y));
    p.y = pack_h2(__float2half_rn(v.z), __float2half_rn(v.w));
    *(uint2*)(g_xh + 4 * i) = p;
}

// ---------------------------------------------------------------------------
// Kernel 2: W_eff fp32 build -> fp16 (unchanged, known-good)
// ---------------------------------------------------------------------------
__global__ void __launch_bounds__(128, 1) prep_kernel(
        const int* __restrict__ packed, const float* __restrict__ cb,
        const float* __restrict__ norms, const float* __restrict__ rot) {
    extern __shared__ float sm[];
    float* Rs = sm;            // [128 j][128 k] fp32, 64KB
    float* Cs = sm + 16384;    // [32 r][128 j] fp32, 16KB
    __shared__ float cbs[16];

    const int t = threadIdx.x;
    const int g = blockIdx.y;
    const int row0 = blockIdx.x * 32;

    if (t < 16) cbs[t] = cb[t];
    const float4* rg = (const float4*)(rot + (size_t)g * 16384);
    float4* Rs4 = (float4*)Rs;
#pragma unroll 8
    for (int i = t; i < 4096; i += 128) Rs4[i] = rg[i];
    __syncthreads();

#pragma unroll 4
    for (int i = t; i < 2048; i += 128) {
        int r = i >> 6, ii = i & 63;
        int v = packed[(size_t)(row0 + r) * 2048 + g * 64 + ii] & 0xFF;
        Cs[r * 128 + 2 * ii]     = cbs[v & 0xF];
        Cs[r * 128 + 2 * ii + 1] = cbs[(v >> 4) & 0xF];
    }
    __syncthreads();

    const int tx = t & 31;
    const int ty = t >> 5;
    const int kq = tx * 4;

    float acc[8][4];
#pragma unroll
    for (int r = 0; r < 8; r++)
#pragma unroll
        for (int q = 0; q < 4; q++) acc[r][q] = 0.f;

    for (int j = 0; j < 128; j += 4) {
        float4 R0 = *(const float4*)&Rs[(j + 0) * 128 + kq];
        float4 R1 = *(const float4*)&Rs[(j + 1) * 128 + kq];
        float4 R2 = *(const float4*)&Rs[(j + 2) * 128 + kq];
        float4 R3 = *(const float4*)&Rs[(j + 3) * 128 + kq];
#pragma unroll
        for (int r = 0; r < 8; r++) {
            float4 c = *(const float4*)&Cs[(ty * 8 + r) * 128 + j];
            acc[r][0] += c.x * R0.x + c.y * R1.x + c.z * R2.x + c.w * R3.x;
            acc[r][1] += c.x * R0.y + c.y * R1.y + c.z * R2.y + c.w * R3.y;
            acc[r][2] += c.x * R0.z + c.y * R1.z + c.z * R2.z + c.w * R3.z;
            acc[r][3] += c.x * R0.w + c.y * R1.w + c.z * R2.w + c.w * R3.w;
        }
    }

#pragma unroll
    for (int r = 0; r < 8; r++) {
        int n = row0 + ty * 8 + r;
        float s = norms[(size_t)n * 32 + g] * INV_SCALE;
        __half h[4];
#pragma unroll
        for (int q = 0; q < 4; q++) h[q] = __float2half_rn(acc[r][q] * s);
        size_t o = (size_t)n * 4096 + g * 128 + kq;
        *(uint2*)(g_wh + o) = make_uint2(pack_h2(h[0], h[1]), pack_h2(h[2], h[3]));
    }
}

// ---------------------------------------------------------------------------
// Kernel 3: GEMM. BM=128 BN=256 BK=64, 3-stage cp.async, 16 warps (4x4),
// warp tile 32x64. 144B rows (odd 16B stride) -> conflict-free ldsm/cp.async.
// ---------------------------------------------------------------------------
constexpr int STAGES = 3;
constexpr int ROWB   = 144;                 // 128B data + 16B pad
constexpr int ATILEB = 128 * ROWB;          // 18432
constexpr int BTILEB = 256 * ROWB;          // 36864
constexpr int STG    = ATILEB + BTILEB;     // 55296
constexpr int GEMM_SMEM = STAGES * STG;     // 165888

__global__ void __launch_bounds__(512, 1) gemm_kernel(float* __restrict__ out) {
    extern __shared__ __align__(128) char smem[];
    const uint32_t sb = smem_u32(smem);
    const int tid = threadIdx.x, lid = tid & 31, wid = tid >> 5;
    const int wm = wid & 3, wn = wid >> 2;          // warp grid 4 (M) x 4 (N)
    const size_t m0 = (size_t)blockIdx.x * 128;     // mblk fast: wave shares B in L2
    const size_t n0 = (size_t)blockIdx.y * 256;

    float acc[2][8][4];
#pragma unroll
    for (int mi = 0; mi < 2; mi++)
#pragma unroll
        for (int ni = 0; ni < 8; ni++)
#pragma unroll
            for (int q = 0; q < 4; q++) acc[mi][ni][q] = 0.f;

    auto issue = [&](int nk) {
        if (nk < 64) {
            const uint32_t st = sb + (nk % STAGES) * STG;
            const size_t kcol = (size_t)nk * 64;
#pragma unroll
            for (int p = 0; p < 2; p++) {           // A: 128 rows x 8 chunks
                int ch = tid + 512 * p; int r = ch >> 3, c = ch & 7;
                cp16(st + (uint32_t)(r * ROWB + c * 16),
                     g_xh + (m0 + r) * 4096 + kcol + c * 8);
            }
#pragma unroll
            for (int p = 0; p < 4; p++) {           // B: 256 rows x 8 chunks
                int ch = tid + 512 * p; int r = ch >> 3, c = ch & 7;
                cp16(st + ATILEB + (uint32_t)(r * ROWB + c * 16),
                     g_wh + (n0 + r) * 4096 + kcol + c * 8);
            }
        }
        CP_COMMIT();
    };

    issue(0);
    issue(1);

    const int rsel = lid & 15, csel = lid >> 4;

    for (int kt = 0; kt < 64; kt++) {
        CP_WAIT(STAGES - 2);
        __syncthreads();
        issue(kt + 2);          // slot (kt+2)%3 == (kt-1)%3, consumed last iter

        const uint32_t st = sb + (kt % STAGES) * STG;
#pragma unroll
        for (int kk = 0; kk < 4; kk++) {
            uint32_t a[2][4], b[4][4];
            const uint32_t kadd = (uint32_t)(kk * 32 + csel * 16);
#pragma unroll
            for (int mi = 0; mi < 2; mi++)
                ldsm_x4(a[mi], st + (wm * 32 + mi * 16 + rsel) * ROWB + kadd);
#pragma unroll
            for (int nh = 0; nh < 4; nh++)
                ldsm_x4(b[nh], st + ATILEB + (wn * 64 + nh * 16 + rsel) * ROWB + kadd);
#pragma unroll
            for (int mi = 0; mi < 2; mi++)
#pragma unroll
                for (int ni = 0; ni < 8; ni++) {
                    const int nh = ni >> 1, s2 = ni & 1;
                    mma16816(acc[mi][ni], a[mi], b[nh][s2], b[nh][s2 + 2]);
                }
        }
    }

    const int r0 = lid >> 2, c0 = (lid & 3) * 2;
#pragma unroll
    for (int mi = 0; mi < 2; mi++)
#pragma unroll
        for (int ni = 0; ni < 8; ni++) {
            size_t m = m0 + wm * 32 + mi * 16 + r0;
            size_t n = n0 + wn * 64 + ni * 8 + c0;
            *(float2*)(out + m * 4096 + n) =
                make_float2(acc[mi][ni][0], acc[mi][ni][1]);
            *(float2*)(out + (m + 8) * 4096 + n) =
                make_float2(acc[mi][ni][2], acc[mi][ni][3]);
        }
}

// ---------------------------------------------------------------------------
extern "C" void kernel_launch(void* const* d_in, const int* in_sizes, int n_in,
                              void* d_out, int out_size) {
    const float* x      = (const float*)d_in[0];
    const int*   packed = (const int*)  d_in[1];
    const float* cb     = (const float*)d_in[2];
    const float* norms  = (const float*)d_in[3];
    const float* rot    = (const float*)d_in[4];
    float* out = (float*)d_out;

    cudaFuncSetAttribute(prep_kernel, cudaFuncAttributeMaxDynamicSharedMemorySize, 81920);
    cudaFuncSetAttribute(gemm_kernel, cudaFuncAttributeMaxDynamicSharedMemorySize, GEMM_SMEM);

    convert_x_kernel<<<32768, 256>>>((const float4*)x);
    prep_kernel<<<dim3(128, 32), 128, 81920>>>(packed, cb, norms, rot);
    gemm_kernel<<<dim3(64, 16), 512, GEMM_SMEM>>>(out);
}

// round 8
// speedup vs baseline: 2.2694x; 1.1237x over previous
#include <cuda_runtime.h>
#include <cuda_fp16.h>
#include <cstdint>
#include <cstddef>

// ============================================================================
// TurboQuantLinear: out[t,n] = sum_k x[t,k] * W_eff[n,k]
//   W_eff[n, g*128+k] = (norms[n,g]/sqrt(128)) * sum_j codes[n,g,j]*R[g,j,k]
// sm_100 (no 'a'). ldmatrix + mma.sync m16n8k16 fp16->fp32.
// R8: fix R7's prep smem stride bug (rows are 256B of data -> PROWB=272,
// not 144). Main GEMM unchanged (at legacy HMMA issue floor ~290 TF/s).
// ============================================================================

constexpr int TOKENS = 8192;
constexpr int KDIM   = 4096;
constexpr int NDIM   = 4096;
constexpr float INV_SCALE = 0.08838834764831845f; // 1/sqrt(128)

__device__ __align__(16) __half g_xh[(size_t)TOKENS * KDIM];   // 64 MB
__device__ __align__(16) __half g_wh[(size_t)NDIM * KDIM];     // 32 MB
__device__ __align__(16) __half g_rt[(size_t)32 * 128 * 128];  // 1 MB, Rt[g][k][j]

// ---- PTX helpers -----------------------------------------------------------
__device__ __forceinline__ uint32_t smem_u32(const void* p) {
    uint32_t a;
    asm("{ .reg .u64 t; cvta.to.shared.u64 t, %1; cvt.u32.u64 %0, t; }"
        : "=r"(a) : "l"(p));
    return a;
}
__device__ __forceinline__ void cp16(uint32_t s, const void* g) {
    asm volatile("cp.async.cg.shared.global [%0], [%1], 16;" :: "r"(s), "l"(g));
}
#define CP_COMMIT() asm volatile("cp.async.commit_group;" ::: "memory")
#define CP_WAIT(n)  asm volatile("cp.async.wait_group %0;" :: "n"(n) : "memory")

__device__ __forceinline__ void ldsm_x4(uint32_t (&r)[4], uint32_t addr) {
    asm volatile("ldmatrix.sync.aligned.m8n8.x4.shared.b16 {%0,%1,%2,%3}, [%4];"
        : "=r"(r[0]), "=r"(r[1]), "=r"(r[2]), "=r"(r[3]) : "r"(addr));
}
__device__ __forceinline__ void mma16816(float (&d)[4], const uint32_t (&a)[4],
                                         uint32_t b0, uint32_t b1) {
    asm volatile("mma.sync.aligned.m16n8k16.row.col.f32.f16.f16.f32 "
        "{%0,%1,%2,%3}, {%4,%5,%6,%7}, {%8,%9}, {%0,%1,%2,%3};"
        : "+f"(d[0]), "+f"(d[1]), "+f"(d[2]), "+f"(d[3])
        : "r"(a[0]), "r"(a[1]), "r"(a[2]), "r"(a[3]), "r"(b0), "r"(b1));
}
__device__ __forceinline__ uint32_t pack_h2(__half a, __half b) {
    return (uint32_t)__half_as_ushort(a) | ((uint32_t)__half_as_ushort(b) << 16);
}

// ---------------------------------------------------------------------------
// Kernel 1: x fp32 -> fp16
// ---------------------------------------------------------------------------
__global__ void __launch_bounds__(256) convert_x_kernel(const float4* __restrict__ x) {
    size_t i = (size_t)blockIdx.x * blockDim.x + threadIdx.x;
    float4 v = x[i];
    uint2 p;
    p.x = pack_h2(__float2half_rn(v.x), __float2half_rn(v.y));
    p.y = pack_h2(__float2half_rn(v.z), __float2half_rn(v.w));
    *(uint2*)(g_xh + 4 * i) = p;
}

// ---------------------------------------------------------------------------
// Kernel 2a: Rt[g][k][j] = fp16(rot[g][j][k]). One block per group.
// ---------------------------------------------------------------------------
__global__ void __launch_bounds__(256) transpose_r_kernel(const float* __restrict__ rot) {
    extern __shared__ float rs[];           // 128*129 floats = 66048 B
    const int t = threadIdx.x;
    const int g = blockIdx.x;
    const float* rg = rot + (size_t)g * 16384;
#pragma unroll 16
    for (int it = 0; it < 64; it++) {
        int idx = t + 256 * it;             // j*128 + k
        rs[(idx >> 7) * 129 + (idx & 127)] = rg[idx];
    }
    __syncthreads();
    __half* og = g_rt + (size_t)g * 16384;
#pragma unroll 16
    for (int it = 0; it < 64; it++) {
        int idx = t + 256 * it;             // k*128 + j
        int k = idx >> 7, j = idx & 127;
        og[idx] = __float2half_rn(rs[j * 129 + k]);
    }
}

// ---------------------------------------------------------------------------
// Kernel 2b: prep on tensor cores.
//   Per block: 128 N-rows x one group. codes[128r][128j] fp16 (decoded into
//   smem) @ Rt[128k][128j] fp16 -> W_eff rows, scaled by norms/sqrt(128).
//   Rows hold 256B data; PROWB=272 (16B pad, odd 16B stride -> conflict-free).
// ---------------------------------------------------------------------------
constexpr int PROWB = 272;                  // 256B data + 16B pad
constexpr int PTILE = 128 * PROWB;          // 34816
constexpr int PREP_SMEM = 2 * PTILE;        // 69632

__global__ void __launch_bounds__(256, 1) prep_mma_kernel(
        const int* __restrict__ packed, const float* __restrict__ cb,
        const float* __restrict__ norms) {
    extern __shared__ __align__(128) char psm[];
    __shared__ float cbs[16];
    __shared__ float snorm[128];
    const uint32_t sb = smem_u32(psm);
    const int t = threadIdx.x, lid = t & 31, wid = t >> 5;
    const int g = blockIdx.y;
    const int row0 = blockIdx.x * 128;

    if (t < 16) cbs[t] = cb[t];
    if (t < 128) snorm[t] = norms[(size_t)(row0 + t) * 32 + g] * INV_SCALE;

    // Rt tile: 128 rows x 256B data -> 16 chunks of 16B per row
#pragma unroll
    for (int p = 0; p < 8; p++) {
        int ch = t + 256 * p; int r = ch >> 4, c = ch & 15;
        cp16(sb + PTILE + (uint32_t)(r * PROWB + c * 16),
             g_rt + (size_t)g * 16384 + r * 128 + c * 8);
    }
    CP_COMMIT();
    __syncthreads();                         // cbs visible for decode

    // decode codes: 128 rows x 64 packed ints -> fp16 pairs (4B per int)
#pragma unroll 8
    for (int it = 0; it < 32; it++) {
        int idx = t + 256 * it;              // r*64 + ii
        int r = idx >> 6, ii = idx & 63;
        int v = packed[(size_t)(row0 + r) * 2048 + g * 64 + ii] & 0xFF;
        *(uint32_t*)(psm + r * PROWB + ii * 4) =
            pack_h2(__float2half_rn(cbs[v & 0xF]), __float2half_rn(cbs[(v >> 4) & 0xF]));
    }
    CP_WAIT(0);
    __syncthreads();

    const int wm = wid & 1, wn = wid >> 1;   // 2 (M rows) x 4 (N = k_out)
    const int rsel = lid & 15, csel = lid >> 4;

    float acc[4][4][4];
#pragma unroll
    for (int mi = 0; mi < 4; mi++)
#pragma unroll
        for (int ni = 0; ni < 4; ni++)
#pragma unroll
            for (int q = 0; q < 4; q++) acc[mi][ni][q] = 0.f;

#pragma unroll
    for (int k16 = 0; k16 < 8; k16++) {      // over j
        uint32_t a[4][4], b[2][4];
        const uint32_t kadd = (uint32_t)(k16 * 32 + csel * 16);
#pragma unroll
        for (int mi = 0; mi < 4; mi++)
            ldsm_x4(a[mi], sb + (wm * 64 + mi * 16 + rsel) * PROWB + kadd);
#pragma unroll
        for (int nh = 0; nh < 2; nh++)
            ldsm_x4(b[nh], sb + PTILE + (wn * 32 + nh * 16 + rsel) * PROWB + kadd);
#pragma unroll
        for (int mi = 0; mi < 4; mi++)
#pragma unroll
            for (int ni = 0; ni < 4; ni++) {
                const int nh = ni >> 1, s2 = ni & 1;
                mma16816(acc[mi][ni], a[mi], b[nh][s2], b[nh][s2 + 2]);
            }
    }

    const int r0 = lid >> 2, c0 = (lid & 3) * 2;
#pragma unroll
    for (int mi = 0; mi < 4; mi++) {
        const int mloc = wm * 64 + mi * 16 + r0;
        const float s0 = snorm[mloc], s1 = snorm[mloc + 8];
#pragma unroll
        for (int ni = 0; ni < 4; ni++) {
            const int kout = wn * 32 + ni * 8 + c0;
            size_t o = (size_t)(row0 + mloc) * 4096 + g * 128 + kout;
            *(uint32_t*)(g_wh + o) =
                pack_h2(__float2half_rn(acc[mi][ni][0] * s0),
                        __float2half_rn(acc[mi][ni][1] * s0));
            *(uint32_t*)(g_wh + o + 8 * 4096) =
                pack_h2(__float2half_rn(acc[mi][ni][2] * s1),
                        __float2half_rn(acc[mi][ni][3] * s1));
        }
    }
}

// ---------------------------------------------------------------------------
// Kernel 3: GEMM (unchanged from R6, measured 1095 total). BM=128 BN=256
// BK=64, 3 stages, 16 warps, warp tile 32x64, 144B padded rows.
// ---------------------------------------------------------------------------
constexpr int STAGES = 3;
constexpr int ROWB   = 144;
constexpr int ATILEB = 128 * ROWB;
constexpr int BTILEB = 256 * ROWB;
constexpr int STG    = ATILEB + BTILEB;
constexpr int GEMM_SMEM = STAGES * STG;     // 165888

__global__ void __launch_bounds__(512, 1) gemm_kernel(float* __restrict__ out) {
    extern __shared__ __align__(128) char smem[];
    const uint32_t sb = smem_u32(smem);
    const int tid = threadIdx.x, lid = tid & 31, wid = tid >> 5;
    const int wm = wid & 3, wn = wid >> 2;
    const size_t m0 = (size_t)blockIdx.x * 128;
    const size_t n0 = (size_t)blockIdx.y * 256;

    float acc[2][8][4];
#pragma unroll
    for (int mi = 0; mi < 2; mi++)
#pragma unroll
        for (int ni = 0; ni < 8; ni++)
#pragma unroll
            for (int q = 0; q < 4; q++) acc[mi][ni][q] = 0.f;

    auto issue = [&](int nk) {
        if (nk < 64) {
            const uint32_t st = sb + (nk % STAGES) * STG;
            const size_t kcol = (size_t)nk * 64;
#pragma unroll
            for (int p = 0; p < 2; p++) {
                int ch = tid + 512 * p; int r = ch >> 3, c = ch & 7;
                cp16(st + (uint32_t)(r * ROWB + c * 16),
                     g_xh + (m0 + r) * 4096 + kcol + c * 8);
            }
#pragma unroll
            for (int p = 0; p < 4; p++) {
                int ch = tid + 512 * p; int r = ch >> 3, c = ch & 7;
                cp16(st + ATILEB + (uint32_t)(r * ROWB + c * 16),
                     g_wh + (n0 + r) * 4096 + kcol + c * 8);
            }
        }
        CP_COMMIT();
    };

    issue(0);
    issue(1);

    const int rsel = lid & 15, csel = lid >> 4;

    for (int kt = 0; kt < 64; kt++) {
        CP_WAIT(STAGES - 2);
        __syncthreads();
        issue(kt + 2);

        const uint32_t st = sb + (kt % STAGES) * STG;
#pragma unroll
        for (int kk = 0; kk < 4; kk++) {
            uint32_t a[2][4], b[4][4];
            const uint32_t kadd = (uint32_t)(kk * 32 + csel * 16);
#pragma unroll
            for (int mi = 0; mi < 2; mi++)
                ldsm_x4(a[mi], st + (wm * 32 + mi * 16 + rsel) * ROWB + kadd);
#pragma unroll
            for (int nh = 0; nh < 4; nh++)
                ldsm_x4(b[nh], st + ATILEB + (wn * 64 + nh * 16 + rsel) * ROWB + kadd);
#pragma unroll
            for (int mi = 0; mi < 2; mi++)
#pragma unroll
                for (int ni = 0; ni < 8; ni++) {
                    const int nh = ni >> 1, s2 = ni & 1;
                    mma16816(acc[mi][ni], a[mi], b[nh][s2], b[nh][s2 + 2]);
                }
        }
    }

    const int r0 = lid >> 2, c0 = (lid & 3) * 2;
#pragma unroll
    for (int mi = 0; mi < 2; mi++)
#pragma unroll
        for (int ni = 0; ni < 8; ni++) {
            size_t m = m0 + wm * 32 + mi * 16 + r0;
            size_t n = n0 + wn * 64 + ni * 8 + c0;
            *(float2*)(out + m * 4096 + n) =
                make_float2(acc[mi][ni][0], acc[mi][ni][1]);
            *(float2*)(out + (m + 8) * 4096 + n) =
                make_float2(acc[mi][ni][2], acc[mi][ni][3]);
        }
}

// ---------------------------------------------------------------------------
extern "C" void kernel_launch(void* const* d_in, const int* in_sizes, int n_in,
                              void* d_out, int out_size) {
    const float* x      = (const float*)d_in[0];
    const int*   packed = (const int*)  d_in[1];
    const float* cb     = (const float*)d_in[2];
    const float* norms  = (const float*)d_in[3];
    const float* rot    = (const float*)d_in[4];
    float* out = (float*)d_out;

    cudaFuncSetAttribute(transpose_r_kernel, cudaFuncAttributeMaxDynamicSharedMemorySize, 66048);
    cudaFuncSetAttribute(prep_mma_kernel,   cudaFuncAttributeMaxDynamicSharedMemorySize, PREP_SMEM);
    cudaFuncSetAttribute(gemm_kernel,       cudaFuncAttributeMaxDynamicSharedMemorySize, GEMM_SMEM);

    convert_x_kernel<<<32768, 256>>>((const float4*)x);
    transpose_r_kernel<<<32, 256, 66048>>>(rot);
    prep_mma_kernel<<<dim3(32, 32), 256, PREP_SMEM>>>(packed, cb, norms);
    gemm_kernel<<<dim3(64, 16), 512, GEMM_SMEM>>>(out);
}